// round 16
// baseline (speedup 1.0000x reference)
#include <cuda_runtime.h>
#include <cuda_bf16.h>
#include <cstdint>

#define Bsz  512
#define Ssz  1024
#define Esz  48
#define Hsz  128
#define NCLS 2000
#define VOCAB 50257
#define NB   8                 // batches per CTA (MMA n dim)
#define NCTA (Bsz / NB)        // 64
#define NKK  8                 // K chunks of 16 (h only: 128 = 8*16)
#define NFR  (32 * NKK)        // 256 A-fragments per CTA
#define FRW  (NKK * 4)         // 32 fragments per warp (8 k x 4 gates)
#define SROW 68                // state row stride in u32 (64 used; ==4 mod 32)

// Prepared parameters.
// Fragment images: u32 index = fragblk*128 + lane*4 + ri,
//   fragblk = w*FRW + kk*4 + g  ->  W rows g*128 + w*16 + r  (warp = j-slice)
__device__ uint32_t g_whiFrag[NFR * 128];
__device__ uint32_t g_wloFrag[NFR * 128];
__device__ float    g_wihT[Esz * 512];        // w_ih transposed (for prep2)
__device__ float    g_wfcT[Hsz * NCLS];
__device__ float    g_hfin[Bsz * Hsz];
// Token-gate table: xg[token][perm(g,j)] = w_ih(g,j)·emb[token] + bias(g,j).
// perm(g,j) = (j>>4)*64 + ((j>>3)&1)*32 + (j&7)*4 + g  (fragment-aligned).
__device__ float    g_tokGate[VOCAB * 512];   // 103 MB

__device__ __forceinline__ float tanha(float x) {
    float y; asm("tanh.approx.f32 %0, %1;" : "=f"(y) : "f"(x)); return y;
}
__device__ __forceinline__ float siga(float x) { return fmaf(0.5f, tanha(0.5f * x), 0.5f); }

// m16n8k16 bf16 MMA, fp32 accumulate (baseline PTX, sm_80+).
__device__ __forceinline__ void mma(float* d, uint4 a, uint32_t b0, uint32_t b1) {
    asm volatile("mma.sync.aligned.m16n8k16.row.col.f32.bf16.bf16.f32 "
        "{%0,%1,%2,%3}, {%4,%5,%6,%7}, {%8,%9}, {%0,%1,%2,%3};"
        : "+f"(d[0]), "+f"(d[1]), "+f"(d[2]), "+f"(d[3])
        : "r"(a.x), "r"(a.y), "r"(a.z), "r"(a.w), "r"(b0), "r"(b1));
}

// ---------------------------------------------------------------------------
// Prep: w_hh hi/lo fragments, w_ih transpose, fc transpose.
// ---------------------------------------------------------------------------
__global__ void prep_kernel(const float* __restrict__ w_ih, const float* __restrict__ w_hh,
                            const float* __restrict__ w_fc) {
    int i = blockIdx.x * blockDim.x + threadIdx.x;
    if (i < NFR * 128) {
        int fragblk = i >> 7, rem = i & 127;
        int lane = rem >> 2, ri = rem & 3;
        int w = fragblk / FRW, f = fragblk % FRW, kk = f >> 2, g = f & 3;
        int r  = (lane >> 2) + (ri & 1) * 8;
        int c0 = (lane & 3) * 2 + (ri >> 1) * 8;
        int R = g * 128 + w * 16 + r;
        int K = kk * 16 + c0;                  // always < 128 -> w_hh
        float v0 = w_hh[R * Hsz + K];
        float v1 = w_hh[R * Hsz + K + 1];
        __nv_bfloat16 h0 = __float2bfloat16(v0), h1 = __float2bfloat16(v1);
        __nv_bfloat16 l0 = __float2bfloat16(v0 - __bfloat162float(h0));
        __nv_bfloat16 l1 = __float2bfloat16(v1 - __bfloat162float(h1));
        g_whiFrag[i] = (uint32_t)__bfloat16_as_ushort(h0) | ((uint32_t)__bfloat16_as_ushort(h1) << 16);
        g_wloFrag[i] = (uint32_t)__bfloat16_as_ushort(l0) | ((uint32_t)__bfloat16_as_ushort(l1) << 16);
    }
    if (i < Esz * 512) {
        int e = i / 512, r = i % 512;
        g_wihT[i] = w_ih[r * Esz + e];
    }
    if (i < Hsz * NCLS) {
        int k = i / NCLS, n = i % NCLS;
        g_wfcT[i] = w_fc[n * Hsz + k];
    }
}

// ---------------------------------------------------------------------------
// Prep2: token-gate table. 2 tokens per thread, coalesced w_ihT reads.
// ---------------------------------------------------------------------------
__global__ void prep2_kernel(const float* __restrict__ emb,
                             const float* __restrict__ b_ih,
                             const float* __restrict__ b_hh) {
    const int i = blockIdx.x * blockDim.x + threadIdx.x;
    const int NTP = (VOCAB + 1) / 2;           // token pairs
    if (i >= NTP * 512) return;
    const int r = i & 511, tp = i >> 9;
    const int t0 = tp * 2, t1 = t0 + 1;
    const bool h1 = (t1 < VOCAB);
    const float bias = b_ih[r] + b_hh[r];
    float a0 = bias, a1 = bias;
    const float* e0 = emb + (size_t)t0 * Esz;
    const float* e1 = emb + (size_t)t1 * Esz;
    #pragma unroll 8
    for (int e = 0; e < Esz; e++) {
        const float wv = g_wihT[e * 512 + r];
        a0 = fmaf(wv, __ldg(&e0[e]), a0);
        if (h1) a1 = fmaf(wv, __ldg(&e1[e]), a1);
    }
    const int g = r >> 7, j = r & 127;
    const int perm = (j >> 4) * 64 + ((j >> 3) & 1) * 32 + (j & 7) * 4 + g;
    g_tokGate[(size_t)t0 * 512 + perm] = a0;
    if (h1) g_tokGate[(size_t)t1 * 512 + perm] = a1;
}

// ---------------------------------------------------------------------------
// LSTM recurrence: HMMA over h only (8 chunks x 4 gates x 3 terms = 96 MMA),
// fp32 input-part gathered from g_tokGate (prefetched one step ahead).
// ---------------------------------------------------------------------------
struct alignas(16) Smem {
    uint32_t whiA[NFR * 128];      // 128 KB fragment image of Whi (w_hh)
    uint32_t sHi[2][NB * SROW];    // h state hi, double-buffered
    uint32_t sLo[2][NB * SROW];    // h state lo
};

__device__ __forceinline__ void write_state(uint32_t* hiB, uint32_t* loB,
                                            int b, int k, float v) {
    __nv_bfloat16 hi = __float2bfloat16(v);
    __nv_bfloat16 lo = __float2bfloat16(v - __bfloat162float(hi));
    const int kp = k >> 1, hf = k & 1;
    ((uint16_t*)&hiB[b * SROW + kp])[hf] = __bfloat16_as_ushort(hi);
    ((uint16_t*)&loB[b * SROW + kp])[hf] = __bfloat16_as_ushort(lo);
}

__global__ void __launch_bounds__(256, 1)
lstm_kernel(const int* __restrict__ x) {
    extern __shared__ char smraw[];
    Smem* s = (Smem*)smraw;
    const int tid = threadIdx.x;
    const int w   = tid >> 5, l = tid & 31;
    const int B0  = blockIdx.x * NB;

    // Stage Whi fragments; zero both state buffers.
    for (int i = tid; i < NFR * 128 / 4; i += 256)
        ((uint4*)s->whiA)[i] = ((const uint4*)g_whiFrag)[i];
    for (int i = tid; i < 2 * NB * SROW; i += 256) {
        (&s->sHi[0][0])[i] = 0;
        (&s->sLo[0][0])[i] = 0;
    }

    // Wlo fragments: stationary in registers (32 uint4 = 128 regs).
    uint4 wlo[FRW];
    #pragma unroll
    for (int f = 0; f < FRW; f++)
        wlo[f] = ((const uint4*)g_wloFrag)[(w * FRW + f) * 32 + l];

    // Lane cells: j = w*16 + jh*8 + rr ; b = bc + {0,1}.
    const int rr = l >> 2;
    const int bc = (l & 3) * 2;
    const int xoff = w * 64 + rr * 4;          // fragment-aligned tokGate offset
    const int b0g = B0 + bc, b1g = B0 + bc + 1;
    float cc[4] = {0, 0, 0, 0};

    // Step-0 seeds + step-1 tokens.
    float xc[16];                               // [pair 0:b0jh0 1:b0jh1 2:b1jh0 3:b1jh1][g]
    int tv0, tv1;
    {
        const int t0 = __ldg(&x[b0g * Ssz]);
        const int t1 = __ldg(&x[b1g * Ssz]);
        const float* r0 = g_tokGate + (size_t)t0 * 512 + xoff;
        const float* r1 = g_tokGate + (size_t)t1 * 512 + xoff;
        ((float4*)xc)[0] = __ldg((const float4*)r0);
        ((float4*)xc)[1] = __ldg((const float4*)(r0 + 32));
        ((float4*)xc)[2] = __ldg((const float4*)r1);
        ((float4*)xc)[3] = __ldg((const float4*)(r1 + 32));
        tv0 = __ldg(&x[b0g * Ssz + 1]);
        tv1 = __ldg(&x[b1g * Ssz + 1]);
    }
    const uint4* aP = (const uint4*)(s->whiA) + w * FRW * 32 + l;
    __syncthreads();

    for (int st = 0; st < Ssz; st++) {
        const int buf = st & 1, nbuf = buf ^ 1;
        const uint32_t* sh = s->sHi[buf] + (l >> 2) * SROW + (l & 3);
        const uint32_t* sl = s->sLo[buf] + (l >> 2) * SROW + (l & 3);
        uint32_t* nHi = s->sHi[nbuf];
        uint32_t* nLo = s->sLo[nbuf];

        // Prefetch next step's seeds + tokens (fly under HMMA).
        const bool doE = (st + 1 < Ssz);
        float xn[16];
        int tn0 = 0, tn1 = 0;
        if (doE) {
            const float* r0 = g_tokGate + (size_t)tv0 * 512 + xoff;
            const float* r1 = g_tokGate + (size_t)tv1 * 512 + xoff;
            ((float4*)xn)[0] = __ldg((const float4*)r0);
            ((float4*)xn)[1] = __ldg((const float4*)(r0 + 32));
            ((float4*)xn)[2] = __ldg((const float4*)r1);
            ((float4*)xn)[3] = __ldg((const float4*)(r1 + 32));
        }
        if (st + 2 < Ssz) {
            tn0 = __ldg(&x[b0g * Ssz + st + 2]);
            tn1 = __ldg(&x[b1g * Ssz + st + 2]);
        }

        // Accumulators seeded with bias + input-part (from tokGate).
        float d[16];
        #pragma unroll
        for (int g = 0; g < 4; g++) {
            d[g * 4 + 0] = xc[0 + g];    // (jh0, b0)
            d[g * 4 + 1] = xc[8 + g];    // (jh0, b1)
            d[g * 4 + 2] = xc[4 + g];    // (jh1, b0)
            d[g * 4 + 3] = xc[12 + g];   // (jh1, b1)
        }

        // --- HMMA: 8 k-chunks x (3 terms x 4 gates) ---
        #pragma unroll
        for (int kk = 0; kk < NKK; kk++) {
            const uint32_t bhi0 = sh[kk * 8], bhi1 = sh[kk * 8 + 4];
            const uint32_t blo0 = sl[kk * 8], blo1 = sl[kk * 8 + 4];
            uint4 ahi[4];
            #pragma unroll
            for (int g = 0; g < 4; g++) ahi[g] = aP[(kk * 4 + g) * 32];
            #pragma unroll
            for (int g = 0; g < 4; g++) mma(&d[g * 4], ahi[g], bhi0, bhi1);
            #pragma unroll
            for (int g = 0; g < 4; g++) mma(&d[g * 4], ahi[g], blo0, blo1);
            #pragma unroll
            for (int g = 0; g < 4; g++) mma(&d[g * 4], wlo[kk * 4 + g], bhi0, bhi1);
        }

        // --- in-register combine: 4 cells, gates i/f/g/o = d[0/4/8/12 + q] ---
        #pragma unroll
        for (int q = 0; q < 4; q++) {
            const float iv = siga(d[0 + q]);
            const float fv = siga(d[4 + q]);
            const float gv = tanha(d[8 + q]);
            const float ov = siga(d[12 + q]);
            cc[q] = fv * cc[q] + iv * gv;
            const float hv = ov * tanha(cc[q]);
            const int jj = w * 16 + (q >> 1) * 8 + rr;
            if (st == Ssz - 1)
                g_hfin[(B0 + bc + (q & 1)) * Hsz + jj] = hv;
            else
                write_state(nHi, nLo, bc + (q & 1), jj, hv);
        }
        #pragma unroll
        for (int q = 0; q < 16; q++) xc[q] = xn[q];
        tv0 = tn0; tv1 = tn1;
        __syncthreads();
    }
}

// ---------------------------------------------------------------------------
// FC epilogue: out[b][n] = h_fin[b] . w_fc[n] + b_fc[n]
// ---------------------------------------------------------------------------
__global__ void fc_kernel(const float* __restrict__ b_fc, float* __restrict__ out) {
    __shared__ float hs[8][Hsz];
    const int tid = threadIdx.x;
    const int n   = blockIdx.x * 128 + tid;
    const int bb  = blockIdx.y * 8;
    for (int i = tid; i < 8 * Hsz; i += 128)
        hs[i >> 7][i & 127] = g_hfin[(bb + (i >> 7)) * Hsz + (i & 127)];
    __syncthreads();
    if (n >= NCLS) return;
    const float bv = b_fc[n];
    float acc[8];
    #pragma unroll
    for (int i = 0; i < 8; i++) acc[i] = bv;
    #pragma unroll 4
    for (int k = 0; k < Hsz; k++) {
        const float w = g_wfcT[k * NCLS + n];
        #pragma unroll
        for (int i = 0; i < 8; i++) acc[i] = fmaf(hs[i][k], w, acc[i]);
    }
    #pragma unroll
    for (int i = 0; i < 8; i++) out[(bb + i) * NCLS + n] = acc[i];
}

extern "C" void kernel_launch(void* const* d_in, const int* in_sizes, int n_in,
                              void* d_out, int out_size) {
    const int*   x    = (const int*)  d_in[0];
    const float* emb  = (const float*)d_in[1];
    const float* w_ih = (const float*)d_in[2];
    const float* w_hh = (const float*)d_in[3];
    const float* b_ih = (const float*)d_in[4];
    const float* b_hh = (const float*)d_in[5];
    const float* w_fc = (const float*)d_in[6];
    const float* b_fc = (const float*)d_in[7];
    float* out = (float*)d_out;

    static bool attr_set = false;
    if (!attr_set) {
        cudaFuncSetAttribute(lstm_kernel, cudaFuncAttributeMaxDynamicSharedMemorySize,
                             (int)sizeof(Smem));
        attr_set = true;
    }

    prep_kernel<<<1000, 256>>>(w_ih, w_hh, w_fc);
    {
        const int ntp = (VOCAB + 1) / 2;
        const int nthr = ntp * 512;
        prep2_kernel<<<(nthr + 255) / 256, 256>>>(emb, b_ih, b_hh);
    }
    lstm_kernel<<<NCTA, 256, sizeof(Smem)>>>(x);
    fc_kernel<<<dim3((NCLS + 127) / 128, Bsz / 8), 128>>>(b_fc, out);
}

// round 17
// speedup vs baseline: 1.0734x; 1.0734x over previous
#include <cuda_runtime.h>
#include <cuda_bf16.h>
#include <cstdint>

#define Bsz  512
#define Ssz  1024
#define Esz  48
#define Hsz  128
#define NCLS 2000
#define VOCAB 50257
#define NB   8                 // batches per CTA (MMA n dim)
#define NCTA (Bsz / NB)        // 64
#define NKK  8                 // K chunks of 16 (h only: 128 = 8*16)
#define NFR  (32 * NKK)        // 256 A-fragments per CTA
#define FRW  (NKK * 4)         // 32 fragments per warp (8 k x 4 gates)
#define SROW 68                // state row stride in u32 (64 used; ==4 mod 32)
#define TG   32                // tokens per prep2 block

// Prepared parameters.
// Fragment images: u32 index = fragblk*128 + lane*4 + ri,
//   fragblk = w*FRW + kk*4 + g  ->  W rows g*128 + w*16 + r  (warp = j-slice)
__device__ uint32_t g_whiFrag[NFR * 128];
__device__ uint32_t g_wloFrag[NFR * 128];
__device__ float    g_wihT[Esz * 512];        // w_ih transposed (for prep2)
__device__ float    g_wfcT[Hsz * NCLS];
__device__ float    g_hfin[Bsz * Hsz];
// Token-gate table: xg[token][perm(g,j)] = w_ih(g,j)·emb[token] + bias(g,j).
// perm(g,j) = (j>>4)*64 + ((j>>3)&1)*32 + (j&7)*4 + g  (fragment-aligned).
__device__ float    g_tokGate[(size_t)VOCAB * 512];   // 103 MB

__device__ __forceinline__ float tanha(float x) {
    float y; asm("tanh.approx.f32 %0, %1;" : "=f"(y) : "f"(x)); return y;
}
__device__ __forceinline__ float siga(float x) { return fmaf(0.5f, tanha(0.5f * x), 0.5f); }

// m16n8k16 bf16 MMA, fp32 accumulate (baseline PTX, sm_80+).
__device__ __forceinline__ void mma(float* d, uint4 a, uint32_t b0, uint32_t b1) {
    asm volatile("mma.sync.aligned.m16n8k16.row.col.f32.bf16.bf16.f32 "
        "{%0,%1,%2,%3}, {%4,%5,%6,%7}, {%8,%9}, {%0,%1,%2,%3};"
        : "+f"(d[0]), "+f"(d[1]), "+f"(d[2]), "+f"(d[3])
        : "r"(a.x), "r"(a.y), "r"(a.z), "r"(a.w), "r"(b0), "r"(b1));
}

// ---------------------------------------------------------------------------
// Prep: w_hh hi/lo fragments, w_ih transpose, fc transpose.
// ---------------------------------------------------------------------------
__global__ void prep_kernel(const float* __restrict__ w_ih, const float* __restrict__ w_hh,
                            const float* __restrict__ w_fc) {
    int i = blockIdx.x * blockDim.x + threadIdx.x;
    if (i < NFR * 128) {
        int fragblk = i >> 7, rem = i & 127;
        int lane = rem >> 2, ri = rem & 3;
        int w = fragblk / FRW, f = fragblk % FRW, kk = f >> 2, g = f & 3;
        int r  = (lane >> 2) + (ri & 1) * 8;
        int c0 = (lane & 3) * 2 + (ri >> 1) * 8;
        int R = g * 128 + w * 16 + r;
        int K = kk * 16 + c0;                  // always < 128 -> w_hh
        float v0 = w_hh[R * Hsz + K];
        float v1 = w_hh[R * Hsz + K + 1];
        __nv_bfloat16 h0 = __float2bfloat16(v0), h1 = __float2bfloat16(v1);
        __nv_bfloat16 l0 = __float2bfloat16(v0 - __bfloat162float(h0));
        __nv_bfloat16 l1 = __float2bfloat16(v1 - __bfloat162float(h1));
        g_whiFrag[i] = (uint32_t)__bfloat16_as_ushort(h0) | ((uint32_t)__bfloat16_as_ushort(h1) << 16);
        g_wloFrag[i] = (uint32_t)__bfloat16_as_ushort(l0) | ((uint32_t)__bfloat16_as_ushort(l1) << 16);
    }
    if (i < Esz * 512) {
        int e = i / 512, r = i % 512;
        g_wihT[i] = w_ih[r * Esz + e];
    }
    if (i < Hsz * NCLS) {
        int k = i / NCLS, n = i % NCLS;
        g_wfcT[i] = w_fc[n * Hsz + k];
    }
}

// ---------------------------------------------------------------------------
// Prep2 (tiled GEMM): block = (r-chunk, token-group). 32 tokens' emb rows in
// smem (loaded once, contiguous); each thread keeps its w_ih column (48 f) in
// registers and produces 32 outputs. Broadcast LDS, coalesced LDG.
// ---------------------------------------------------------------------------
__global__ void __launch_bounds__(256, 4)
prep2_kernel(const float* __restrict__ emb,
             const float* __restrict__ b_ih,
             const float* __restrict__ b_hh) {
    __shared__ float sEmb[TG * Esz];           // 6 KB
    const int tid = threadIdx.x;
    const int t0  = blockIdx.y * TG;
    const int r   = blockIdx.x * 256 + tid;

    const int nTok = min(TG, VOCAB - t0);
    for (int i = tid; i < nTok * Esz; i += 256)
        sEmb[i] = emb[(size_t)t0 * Esz + i];

    float wv[Esz];
    #pragma unroll
    for (int e = 0; e < Esz; e++)
        wv[e] = g_wihT[e * 512 + r];
    const float bias = b_ih[r] + b_hh[r];

    const int g = r >> 7, j = r & 127;
    const int perm = (j >> 4) * 64 + ((j >> 3) & 1) * 32 + (j & 7) * 4 + g;
    __syncthreads();

    for (int t = 0; t < nTok; t++) {
        float acc = bias;
        #pragma unroll
        for (int e = 0; e < Esz; e++)
            acc = fmaf(wv[e], sEmb[t * Esz + e], acc);
        g_tokGate[(size_t)(t0 + t) * 512 + perm] = acc;
    }
}

// ---------------------------------------------------------------------------
// LSTM recurrence: HMMA over h only (8 chunks x 4 gates x 3 terms = 96 MMA),
// fp32 input-part gathered from g_tokGate (prefetched one step ahead).
// ---------------------------------------------------------------------------
struct alignas(16) Smem {
    uint32_t whiA[NFR * 128];      // 128 KB fragment image of Whi (w_hh)
    uint32_t sHi[2][NB * SROW];    // h state hi, double-buffered
    uint32_t sLo[2][NB * SROW];    // h state lo
};

__device__ __forceinline__ void write_state(uint32_t* hiB, uint32_t* loB,
                                            int b, int k, float v) {
    __nv_bfloat16 hi = __float2bfloat16(v);
    __nv_bfloat16 lo = __float2bfloat16(v - __bfloat162float(hi));
    const int kp = k >> 1, hf = k & 1;
    ((uint16_t*)&hiB[b * SROW + kp])[hf] = __bfloat16_as_ushort(hi);
    ((uint16_t*)&loB[b * SROW + kp])[hf] = __bfloat16_as_ushort(lo);
}

__global__ void __launch_bounds__(256, 1)
lstm_kernel(const int* __restrict__ x) {
    extern __shared__ char smraw[];
    Smem* s = (Smem*)smraw;
    const int tid = threadIdx.x;
    const int w   = tid >> 5, l = tid & 31;
    const int B0  = blockIdx.x * NB;

    // Stage Whi fragments; zero both state buffers.
    for (int i = tid; i < NFR * 128 / 4; i += 256)
        ((uint4*)s->whiA)[i] = ((const uint4*)g_whiFrag)[i];
    for (int i = tid; i < 2 * NB * SROW; i += 256) {
        (&s->sHi[0][0])[i] = 0;
        (&s->sLo[0][0])[i] = 0;
    }

    // Wlo fragments: stationary in registers (32 uint4 = 128 regs).
    uint4 wlo[FRW];
    #pragma unroll
    for (int f = 0; f < FRW; f++)
        wlo[f] = ((const uint4*)g_wloFrag)[(w * FRW + f) * 32 + l];

    // Lane cells: j = w*16 + jh*8 + rr ; b = bc + {0,1}.
    const int rr = l >> 2;
    const int bc = (l & 3) * 2;
    const int xoff = w * 64 + rr * 4;          // fragment-aligned tokGate offset
    const int b0g = B0 + bc, b1g = B0 + bc + 1;
    float cc[4] = {0, 0, 0, 0};

    // Step-0 seeds + step-1 tokens.
    float xc[16];                               // [pair 0:b0jh0 1:b0jh1 2:b1jh0 3:b1jh1][g]
    int tv0, tv1;
    {
        const int t0 = __ldg(&x[b0g * Ssz]);
        const int t1 = __ldg(&x[b1g * Ssz]);
        const float* r0 = g_tokGate + (size_t)t0 * 512 + xoff;
        const float* r1 = g_tokGate + (size_t)t1 * 512 + xoff;
        ((float4*)xc)[0] = __ldg((const float4*)r0);
        ((float4*)xc)[1] = __ldg((const float4*)(r0 + 32));
        ((float4*)xc)[2] = __ldg((const float4*)r1);
        ((float4*)xc)[3] = __ldg((const float4*)(r1 + 32));
        tv0 = __ldg(&x[b0g * Ssz + 1]);
        tv1 = __ldg(&x[b1g * Ssz + 1]);
    }
    const uint4* aP = (const uint4*)(s->whiA) + w * FRW * 32 + l;
    __syncthreads();

    for (int st = 0; st < Ssz; st++) {
        const int buf = st & 1, nbuf = buf ^ 1;
        const uint32_t* sh = s->sHi[buf] + (l >> 2) * SROW + (l & 3);
        const uint32_t* sl = s->sLo[buf] + (l >> 2) * SROW + (l & 3);
        uint32_t* nHi = s->sHi[nbuf];
        uint32_t* nLo = s->sLo[nbuf];

        // Prefetch next step's seeds + tokens (fly under HMMA).
        const bool doE = (st + 1 < Ssz);
        float xn[16];
        int tn0 = 0, tn1 = 0;
        if (doE) {
            const float* r0 = g_tokGate + (size_t)tv0 * 512 + xoff;
            const float* r1 = g_tokGate + (size_t)tv1 * 512 + xoff;
            ((float4*)xn)[0] = __ldg((const float4*)r0);
            ((float4*)xn)[1] = __ldg((const float4*)(r0 + 32));
            ((float4*)xn)[2] = __ldg((const float4*)r1);
            ((float4*)xn)[3] = __ldg((const float4*)(r1 + 32));
        }
        if (st + 2 < Ssz) {
            tn0 = __ldg(&x[b0g * Ssz + st + 2]);
            tn1 = __ldg(&x[b1g * Ssz + st + 2]);
        }

        // Accumulators seeded with bias + input-part (from tokGate).
        float d[16];
        #pragma unroll
        for (int g = 0; g < 4; g++) {
            d[g * 4 + 0] = xc[0 + g];    // (jh0, b0)
            d[g * 4 + 1] = xc[8 + g];    // (jh0, b1)
            d[g * 4 + 2] = xc[4 + g];    // (jh1, b0)
            d[g * 4 + 3] = xc[12 + g];   // (jh1, b1)
        }

        // --- HMMA: 8 k-chunks x (3 terms x 4 gates) ---
        #pragma unroll
        for (int kk = 0; kk < NKK; kk++) {
            const uint32_t bhi0 = sh[kk * 8], bhi1 = sh[kk * 8 + 4];
            const uint32_t blo0 = sl[kk * 8], blo1 = sl[kk * 8 + 4];
            uint4 ahi[4];
            #pragma unroll
            for (int g = 0; g < 4; g++) ahi[g] = aP[(kk * 4 + g) * 32];
            #pragma unroll
            for (int g = 0; g < 4; g++) mma(&d[g * 4], ahi[g], bhi0, bhi1);
            #pragma unroll
            for (int g = 0; g < 4; g++) mma(&d[g * 4], ahi[g], blo0, blo1);
            #pragma unroll
            for (int g = 0; g < 4; g++) mma(&d[g * 4], wlo[kk * 4 + g], bhi0, bhi1);
        }

        // --- in-register combine: 4 cells, gates i/f/g/o = d[0/4/8/12 + q] ---
        #pragma unroll
        for (int q = 0; q < 4; q++) {
            const float iv = siga(d[0 + q]);
            const float fv = siga(d[4 + q]);
            const float gv = tanha(d[8 + q]);
            const float ov = siga(d[12 + q]);
            cc[q] = fv * cc[q] + iv * gv;
            const float hv = ov * tanha(cc[q]);
            const int jj = w * 16 + (q >> 1) * 8 + rr;
            if (st == Ssz - 1)
                g_hfin[(B0 + bc + (q & 1)) * Hsz + jj] = hv;
            else
                write_state(nHi, nLo, bc + (q & 1), jj, hv);
        }
        #pragma unroll
        for (int q = 0; q < 16; q++) xc[q] = xn[q];
        tv0 = tn0; tv1 = tn1;
        __syncthreads();
    }
}

// ---------------------------------------------------------------------------
// FC epilogue: out[b][n] = h_fin[b] . w_fc[n] + b_fc[n]
// ---------------------------------------------------------------------------
__global__ void fc_kernel(const float* __restrict__ b_fc, float* __restrict__ out) {
    __shared__ float hs[8][Hsz];
    const int tid = threadIdx.x;
    const int n   = blockIdx.x * 128 + tid;
    const int bb  = blockIdx.y * 8;
    for (int i = tid; i < 8 * Hsz; i += 128)
        hs[i >> 7][i & 127] = g_hfin[(bb + (i >> 7)) * Hsz + (i & 127)];
    __syncthreads();
    if (n >= NCLS) return;
    const float bv = b_fc[n];
    float acc[8];
    #pragma unroll
    for (int i = 0; i < 8; i++) acc[i] = bv;
    #pragma unroll 4
    for (int k = 0; k < Hsz; k++) {
        const float w = g_wfcT[k * NCLS + n];
        #pragma unroll
        for (int i = 0; i < 8; i++) acc[i] = fmaf(hs[i][k], w, acc[i]);
    }
    #pragma unroll
    for (int i = 0; i < 8; i++) out[(bb + i) * NCLS + n] = acc[i];
}

extern "C" void kernel_launch(void* const* d_in, const int* in_sizes, int n_in,
                              void* d_out, int out_size) {
    const int*   x    = (const int*)  d_in[0];
    const float* emb  = (const float*)d_in[1];
    const float* w_ih = (const float*)d_in[2];
    const float* w_hh = (const float*)d_in[3];
    const float* b_ih = (const float*)d_in[4];
    const float* b_hh = (const float*)d_in[5];
    const float* w_fc = (const float*)d_in[6];
    const float* b_fc = (const float*)d_in[7];
    float* out = (float*)d_out;

    static bool attr_set = false;
    if (!attr_set) {
        cudaFuncSetAttribute(lstm_kernel, cudaFuncAttributeMaxDynamicSharedMemorySize,
                             (int)sizeof(Smem));
        attr_set = true;
    }

    prep_kernel<<<1000, 256>>>(w_ih, w_hh, w_fc);
    prep2_kernel<<<dim3(2, (VOCAB + TG - 1) / TG), 256>>>(emb, b_ih, b_hh);
    lstm_kernel<<<NCTA, 256, sizeof(Smem)>>>(x);
    fc_kernel<<<dim3((NCLS + 127) / 128, Bsz / 8), 128>>>(b_fc, out);
}